// round 14
// baseline (speedup 1.0000x reference)
#include <cuda_runtime.h>
#include <cuda_bf16.h>
#include <math.h>

#define BB 16384
#define LL 32

typedef unsigned long long ull;

// scratch (no allocation allowed)
__device__ float g_z[BB * 8];
__device__ float g_T10[BB];

__device__ __forceinline__ ull pack2(float lo, float hi) {
    ull r; asm("mov.b64 %0,{%1,%2};" : "=l"(r) : "f"(lo), "f"(hi)); return r;
}
__device__ __forceinline__ void unpack2(ull v, float& lo, float& hi) {
    asm("mov.b64 {%0,%1},%2;" : "=f"(lo), "=f"(hi) : "l"(v));
}
__device__ __forceinline__ ull fma2(ull a, ull b, ull c) {
    ull d; asm("fma.rn.f32x2 %0,%1,%2,%3;" : "=l"(d) : "l"(a), "l"(b), "l"(c)); return d;
}
__device__ __forceinline__ ull add2(ull a, ull b) {
    ull d; asm("add.rn.f32x2 %0,%1,%2;" : "=l"(d) : "l"(a), "l"(b)); return d;
}
__device__ __forceinline__ ull shfl64(ull v, int m) {
    float lo, hi; unpack2(v, lo, hi);
    lo = __shfl_xor_sync(0xffffffffu, lo, m);
    hi = __shfl_xor_sync(0xffffffffu, hi, m);
    return pack2(lo, hi);
}

__device__ __forceinline__ float tanh_fast(float x) {
    float e = __expf(2.0f * x);
    return 1.0f - __fdividef(2.0f, e + 1.0f);
}

__device__ __forceinline__ float2 dxval(float s, float2 x0, float2 x1, float2 m0, float2 m1) {
    float s2 = s * s;
    float cx0 = 6.f * s2 - 6.f * s;
    float cm0 = 3.f * s2 - 4.f * s + 1.f;
    float cx1 = -6.f * s2 + 6.f * s;
    float cm1 = 3.f * s2 - 2.f * s;
    float2 r;
    r.x = cx0 * x0.x + cm0 * m0.x + cx1 * x1.x + cm1 * m1.x;
    r.y = cx0 * x0.y + cm0 * m0.y + cx1 * x1.y + cm1 * m1.y;
    return r;
}

// F(s,z) for THREE rows per lane; warp splits k by lane parity g (stride 2)
// and warp half kh (2x2). Same weight LDS serves 3 rows. Rows A/B reduced by
// xor-1 role-split; row C by plain xor-1 butterfly; stage 2 xor-16 kh
// role-split for all. tanh on own j-half; k reassembled by shuffles.
__device__ __forceinline__ void Feval3(const ull* zA, const ull* zB, const ull* zC,
                                       float2 dA, float2 dB, float2 dC,
                                       const float* w1p, const float* w2p,
                                       const ull* b1p, const float* sB2,
                                       int odd, int kh,
                                       ull* kA, ull* kB, ull* kC) {
    ull aA[8], aB[8], aC[8];
#pragma unroll
    for (int j = 0; j < 8; j++) { aA[j] = 0ull; aB[j] = 0ull; aC[j] = 0ull; }

#pragma unroll 4
    for (int t = 0; t < 64; t++) {
        ulonglong2 w1a = *reinterpret_cast<const ulonglong2*>(w1p + t * 16);
        ulonglong2 w1b = *reinterpret_cast<const ulonglong2*>(w1p + t * 16 + 4);
        ull bk = b1p[t * 2];

        ull accA = fma2(w1a.x, zA[0], bk);
        ull accB = fma2(w1a.x, zB[0], bk);
        ull accC = fma2(w1a.x, zC[0], bk);
        accA = fma2(w1a.y, zA[1], accA);
        accB = fma2(w1a.y, zB[1], accB);
        accC = fma2(w1a.y, zC[1], accC);
        accA = fma2(w1b.x, zA[2], accA);
        accB = fma2(w1b.x, zB[2], accB);
        accC = fma2(w1b.x, zC[2], accC);
        accA = fma2(w1b.y, zA[3], accA);
        accB = fma2(w1b.y, zB[3], accB);
        accC = fma2(w1b.y, zC[3], accC);
        float alo, ahi, blo, bhi, clo, chi;
        unpack2(accA, alo, ahi);
        unpack2(accB, blo, bhi);
        unpack2(accC, clo, chi);
        float hA = fmaxf(alo + ahi, 0.f);
        float hB = fmaxf(blo + bhi, 0.f);
        float hC = fmaxf(clo + chi, 0.f);
        ull hhA = pack2(hA, hA);
        ull hhB = pack2(hB, hB);
        ull hhC = pack2(hC, hC);

        const float* base = w2p + t * 32;
        ulonglong2 c0 = *reinterpret_cast<const ulonglong2*>(base);
        ulonglong2 c1 = *reinterpret_cast<const ulonglong2*>(base + 4);
        ulonglong2 c2 = *reinterpret_cast<const ulonglong2*>(base + 8);
        ulonglong2 c3 = *reinterpret_cast<const ulonglong2*>(base + 12);
        aA[0] = fma2(c0.x, hhA, aA[0]); aB[0] = fma2(c0.x, hhB, aB[0]); aC[0] = fma2(c0.x, hhC, aC[0]);
        aA[1] = fma2(c0.y, hhA, aA[1]); aB[1] = fma2(c0.y, hhB, aB[1]); aC[1] = fma2(c0.y, hhC, aC[1]);
        aA[2] = fma2(c1.x, hhA, aA[2]); aB[2] = fma2(c1.x, hhB, aB[2]); aC[2] = fma2(c1.x, hhC, aC[2]);
        aA[3] = fma2(c1.y, hhA, aA[3]); aB[3] = fma2(c1.y, hhB, aB[3]); aC[3] = fma2(c1.y, hhC, aC[3]);
        aA[4] = fma2(c2.x, hhA, aA[4]); aB[4] = fma2(c2.x, hhB, aB[4]); aC[4] = fma2(c2.x, hhC, aC[4]);
        aA[5] = fma2(c2.y, hhA, aA[5]); aB[5] = fma2(c2.y, hhB, aB[5]); aC[5] = fma2(c2.y, hhC, aC[5]);
        aA[6] = fma2(c3.x, hhA, aA[6]); aB[6] = fma2(c3.x, hhB, aB[6]); aC[6] = fma2(c3.x, hhC, aC[6]);
        aA[7] = fma2(c3.y, hhA, aA[7]); aB[7] = fma2(c3.y, hhB, aB[7]); aC[7] = fma2(c3.y, hhC, aC[7]);
    }

    // stage 1: A/B xor-1 role split; C plain xor-1 butterfly
    ull t8[8], c8[8];
#pragma unroll
    for (int j = 0; j < 8; j++) {
        ull give = odd ? aA[j] : aB[j];
        ull keep = odd ? aB[j] : aA[j];
        t8[j] = add2(keep, shfl64(give, 1));
        c8[j] = add2(aC[j], shfl64(aC[j], 1));
    }
    // stage 2: xor-16 kh role split (lane keeps its j-half)
    ull own[4], ownC[4];
#pragma unroll
    for (int i = 0; i < 4; i++) {
        ull give = kh ? t8[i] : t8[4 + i];
        ull keep = kh ? t8[4 + i] : t8[i];
        own[i] = add2(keep, shfl64(give, 16));
        ull giveC = kh ? c8[i] : c8[4 + i];
        ull keepC = kh ? c8[4 + i] : c8[i];
        ownC[i] = add2(keepC, shfl64(giveC, 16));
    }

    float2 dm;
    dm.x = odd ? dB.x : dA.x;
    dm.y = odd ? dB.y : dA.y;
    const float* b2p = sB2 + 8 * kh;

    float o[4], oc[4];
#pragma unroll
    for (int i = 0; i < 4; i++) {
        float u0, u1; unpack2(own[i], u0, u1);
        float t0 = tanh_fast(u0 + b2p[2 * i]);
        float t1 = tanh_fast(u1 + b2p[2 * i + 1]);
        o[i] = t0 * dm.x + t1 * dm.y;
        float v0, v1; unpack2(ownC[i], v0, v1);
        float s0 = tanh_fast(v0 + b2p[2 * i]);
        float s1 = tanh_fast(v1 + b2p[2 * i + 1]);
        oc[i] = s0 * dC.x + s1 * dC.y;
    }
    ull m0 = pack2(o[0], o[1]);
    ull m1 = pack2(o[2], o[3]);
    ull mc0 = pack2(oc[0], oc[1]);
    ull mc1 = pack2(oc[2], oc[3]);

    int hb = kh * 2;
    // A/B: exchange across kh, then rebroadcast across xor-1
    ull ko0 = shfl64(m0, 16);
    ull ko1 = shfl64(m1, 16);
    ull kmy[4];
    kmy[hb]           = m0;
    kmy[hb + 1]       = m1;
    kmy[hb ^ 2]       = ko0;
    kmy[(hb ^ 2) + 1] = ko1;
#pragma unroll
    for (int hh = 0; hh < 4; hh++) {
        ull ko = shfl64(kmy[hh], 1);
        kA[hh] = odd ? ko : kmy[hh];
        kB[hh] = odd ? kmy[hh] : ko;
    }
    // C: identical across xor-1; only kh exchange needed
    ull kco0 = shfl64(mc0, 16);
    ull kco1 = shfl64(mc1, 16);
    kC[hb]           = mc0;
    kC[hb + 1]       = mc1;
    kC[hb ^ 2]       = kco0;
    kC[(hb ^ 2) + 1] = kco1;
}

__device__ __forceinline__ void substep3(ull* zA, ull* zB, ull* zC,
                                         float2 xaA, float2 xbA, float2 m0A, float2 m1A,
                                         float2 xaB, float2 xbB, float2 m0B, float2 m1B,
                                         float2 xaC, float2 xbC, float2 m0C, float2 m1C,
                                         float s0,
                                         const float* w1p, const float* w2p,
                                         const ull* b1p, const float* sB2,
                                         int odd, int kh) {
    float2 dA1 = dxval(s0,         xaA, xbA, m0A, m1A);
    float2 dA2 = dxval(s0 + 0.25f, xaA, xbA, m0A, m1A);
    float2 dA3 = dxval(s0 + 0.5f,  xaA, xbA, m0A, m1A);
    float2 dB1 = dxval(s0,         xaB, xbB, m0B, m1B);
    float2 dB2 = dxval(s0 + 0.25f, xaB, xbB, m0B, m1B);
    float2 dB3 = dxval(s0 + 0.5f,  xaB, xbB, m0B, m1B);
    float2 dC1 = dxval(s0,         xaC, xbC, m0C, m1C);
    float2 dC2 = dxval(s0 + 0.25f, xaC, xbC, m0C, m1C);
    float2 dC3 = dxval(s0 + 0.5f,  xaC, xbC, m0C, m1C);

    const ull C025 = pack2(0.25f, 0.25f);
    const ull C05  = pack2(0.5f, 0.5f);
    const ull C2   = pack2(2.f, 2.f);
    const ull C112 = pack2(1.f / 12.f, 1.f / 12.f);

    ull kcA[4], kcB[4], kcC[4], ksA[4], ksB[4], ksC[4], ztA[4], ztB[4], ztC[4];
    Feval3(zA, zB, zC, dA1, dB1, dC1, w1p, w2p, b1p, sB2, odd, kh, kcA, kcB, kcC);
#pragma unroll
    for (int j = 0; j < 4; j++) {
        ksA[j] = kcA[j]; ztA[j] = fma2(C025, kcA[j], zA[j]);
        ksB[j] = kcB[j]; ztB[j] = fma2(C025, kcB[j], zB[j]);
        ksC[j] = kcC[j]; ztC[j] = fma2(C025, kcC[j], zC[j]);
    }
    Feval3(ztA, ztB, ztC, dA2, dB2, dC2, w1p, w2p, b1p, sB2, odd, kh, kcA, kcB, kcC);
#pragma unroll
    for (int j = 0; j < 4; j++) {
        ksA[j] = fma2(C2, kcA[j], ksA[j]); ztA[j] = fma2(C025, kcA[j], zA[j]);
        ksB[j] = fma2(C2, kcB[j], ksB[j]); ztB[j] = fma2(C025, kcB[j], zB[j]);
        ksC[j] = fma2(C2, kcC[j], ksC[j]); ztC[j] = fma2(C025, kcC[j], zC[j]);
    }
    Feval3(ztA, ztB, ztC, dA2, dB2, dC2, w1p, w2p, b1p, sB2, odd, kh, kcA, kcB, kcC);
#pragma unroll
    for (int j = 0; j < 4; j++) {
        ksA[j] = fma2(C2, kcA[j], ksA[j]); ztA[j] = fma2(C05, kcA[j], zA[j]);
        ksB[j] = fma2(C2, kcB[j], ksB[j]); ztB[j] = fma2(C05, kcB[j], zB[j]);
        ksC[j] = fma2(C2, kcC[j], ksC[j]); ztC[j] = fma2(C05, kcC[j], zC[j]);
    }
    Feval3(ztA, ztB, ztC, dA3, dB3, dC3, w1p, w2p, b1p, sB2, odd, kh, kcA, kcB, kcC);
#pragma unroll
    for (int j = 0; j < 4; j++) {
        zA[j] = fma2(C112, add2(ksA[j], kcA[j]), zA[j]);
        zB[j] = fma2(C112, add2(ksB[j], kcB[j]), zB[j]);
        zC[j] = fma2(C112, add2(ksC[j], kcC[j]), zC[j]);
    }
}

#define GRID1 ((BB + 23) / 24)

__global__ void __launch_bounds__(32, 8)
k1_ode(const float* __restrict__ X_in, const float* __restrict__ fa_in,
       const int* __restrict__ fa_len,
       const float* __restrict__ W_init, const float* __restrict__ b_init,
       const float* __restrict__ W1, const float* __restrict__ b1,
       const float* __restrict__ W2, const float* __restrict__ b2) {
    // padded layouts: kh half-blocks bank-shifted by 16 B
    __shared__ __align__(16) float sW1[2052];
    __shared__ __align__(16) float sW2T[4100];
    __shared__ __align__(16) ull   sB1p[258];
    __shared__ float sB2[16];
    __shared__ float sWI[16];
    __shared__ float sBI[8];
    __shared__ float2 sX[24][33];

    int tid = threadIdx.x;   // 0..31
    for (int i = tid; i < 2048; i += 32) {
        int kk = i >> 3, e = i & 7;
        int h = kk >> 7, jr = kk & 127;
        sW1[h * 1028 + jr * 8 + e] = W1[i];
    }
    for (int i = tid; i < 16 * 256; i += 32) {
        int j = i >> 8;
        int k = i & 255;
        int h = k >> 7, jr = k & 127;
        sW2T[h * 2052 + jr * 16 + j] = W2[i];
    }
    for (int i = tid; i < 256; i += 32) {
        int h = i >> 7, jr = i & 127;
        sB1p[h * 130 + jr] = pack2(b1[i], 0.f);
    }
    if (tid < 16) sB2[tid] = b2[tid];
    if (tid < 16) sWI[tid] = W_init[tid];
    if (tid < 8)  sBI[tid] = b_init[tid];

    int g  = tid & 1;            // k-parity within half (stride 2)
    int kh = (tid >> 4) & 1;     // k-half
    int p  = (tid >> 1) & 7;     // group id, 0..7
    int q0 = g + 2 * kh;         // lane's slot among the row's 4 lanes
    int rowA = blockIdx.x * 24 + p;
    int rowB = rowA + 8;
    int rowC = rowA + 16;        // may exceed BB-1 in last block

    const float* w2p = sW2T + kh * 2052 + g * 16;
    const float* w1p = sW1  + kh * 1028 + g * 8;
    const ull*   b1p = sB1p + kh * 130  + g;

    // prologue for all three rows: mean, normalize, push-zeros-as-shift
#pragma unroll
    for (int rr = 0; rr < 3; rr++) {
        int row = rowA + rr * 8;
        if (row > BB - 1) row = BB - 1;   // clamp (last block row C)
        int rib = p + rr * 8;
        const float* Xr = X_in + row * LL;
        const float* Fr = fa_in + row * LL;
        int fl = fa_len[row];

        float s = 0.f;
        for (int t = q0; t < LL; t += 4) s += Xr[t];
        s += __shfl_xor_sync(0xffffffffu, s, 1);
        s += __shfl_xor_sync(0xffffffffu, s, 16);
        float mean = s / (float)fl;

        int shift = LL - fl;
        int li = 2 * fl - LL - 1;
        float lastX = (li >= 0) ? (Xr[li] / mean) : 0.f;
        float lastF = Fr[fl - 1];

        for (int q = q0; q < LL; q += 4) {
            float fa, xx;
            if (q < shift) { fa = lastF; xx = lastX; }
            else           { fa = Fr[q - shift]; xx = Xr[q - shift] / mean; }
            sX[rib][q] = make_float2(fa, xx);
        }
    }
    __syncwarp();

    float2 x0A = sX[p][0];
    float2 x0B = sX[p + 8][0];
    float2 x0C = sX[p + 16][0];
    ull zA[4], zB[4], zC[4];
#pragma unroll
    for (int j = 0; j < 4; j++) {
        float a0 = sBI[2 * j]     + sWI[4 * j]     * x0A.x + sWI[4 * j + 1] * x0A.y;
        float a1 = sBI[2 * j + 1] + sWI[4 * j + 2] * x0A.x + sWI[4 * j + 3] * x0A.y;
        zA[j] = pack2(a0, a1);
        float b0 = sBI[2 * j]     + sWI[4 * j]     * x0B.x + sWI[4 * j + 1] * x0B.y;
        float b1v = sBI[2 * j + 1] + sWI[4 * j + 2] * x0B.x + sWI[4 * j + 3] * x0B.y;
        zB[j] = pack2(b0, b1v);
        float c0 = sBI[2 * j]     + sWI[4 * j]     * x0C.x + sWI[4 * j + 1] * x0C.y;
        float c1v = sBI[2 * j + 1] + sWI[4 * j + 2] * x0C.x + sWI[4 * j + 3] * x0C.y;
        zC[j] = pack2(c0, c1v);
    }

    float2 xaA = x0A, m0A = make_float2(0.f, 0.f), m1A;
    float2 xaB = x0B, m0B = make_float2(0.f, 0.f), m1B;
    float2 xaC = x0C, m0C = make_float2(0.f, 0.f), m1C;
    for (int i = 0; i < LL - 1; i++) {
        float2 xbA = sX[p][i + 1];
        float2 xbB = sX[p + 8][i + 1];
        float2 xbC = sX[p + 16][i + 1];
        m1A.x = xbA.x - xaA.x;  m1A.y = xbA.y - xaA.y;
        m1B.x = xbB.x - xaB.x;  m1B.y = xbB.y - xaB.y;
        m1C.x = xbC.x - xaC.x;  m1C.y = xbC.y - xaC.y;
        if (i == 0) { m0A = m1A; m0B = m1B; m0C = m1C; }
        substep3(zA, zB, zC, xaA, xbA, m0A, m1A, xaB, xbB, m0B, m1B,
                 xaC, xbC, m0C, m1C, 0.0f, w1p, w2p, b1p, sB2, g, kh);
        substep3(zA, zB, zC, xaA, xbA, m0A, m1A, xaB, xbB, m0B, m1B,
                 xaC, xbC, m0C, m1C, 0.5f, w1p, w2p, b1p, sB2, g, kh);
        m0A = m1A; m0B = m1B; m0C = m1C;
        xaA = xbA; xaB = xbB; xaC = xbC;
    }
    // all 4 lanes of a row hold identical z; lane slot q0 writes [2q0, 2q0+1]
    {
        float a0, a1, b0, b1v, c0, c1v;
        unpack2(zA[q0], a0, a1);
        unpack2(zB[q0], b0, b1v);
        unpack2(zC[q0], c0, c1v);
        g_z[rowA * 8 + 2 * q0]     = a0;
        g_z[rowA * 8 + 2 * q0 + 1] = a1;
        g_z[rowB * 8 + 2 * q0]     = b0;
        g_z[rowB * 8 + 2 * q0 + 1] = b1v;
        if (rowC < BB) {
            g_z[rowC * 8 + 2 * q0]     = c0;
            g_z[rowC * 8 + 2 * q0 + 1] = c1v;
        }
    }
}

// ---------------- k2: readout MLP with smem-cached Wr2 ----------------
#define K2_W2   0                    // 200*201 floats
#define K2_W1   (200 * 201)          // 1600
#define K2_B1   (K2_W1 + 1600)       // 200
#define K2_B2   (K2_B1 + 200)        // 200
#define K2_W3   (K2_B2 + 200)        // 200
#define K2_H1   (K2_W3 + 200)        // 8 warps * 1600
#define K2_SMEM_FLOATS (K2_H1 + 8 * 1600)
#define K2_SMEM_BYTES  (K2_SMEM_FLOATS * 4)

__global__ void __launch_bounds__(256, 1)
k2_readout(const float* __restrict__ Wr1, const float* __restrict__ br1,
           const float* __restrict__ Wr2, const float* __restrict__ br2,
           const float* __restrict__ Wr3, const float* __restrict__ br3) {
    extern __shared__ __align__(16) float sm[];
    int tid = threadIdx.x;
    int lane = tid & 31;
    int w = tid >> 5;

    for (int i = tid; i < 200 * 200; i += 256)
        sm[K2_W2 + (i / 200) * 201 + (i % 200)] = Wr2[i];
    for (int i = tid; i < 1600; i += 256) sm[K2_W1 + i] = Wr1[i];
    for (int i = tid; i < 200; i += 256) {
        sm[K2_B1 + i] = br1[i];
        sm[K2_B2 + i] = br2[i];
        sm[K2_W3 + i] = Wr3[i];
    }
    __syncthreads();

    float* h1w = sm + K2_H1 + w * 1600;
    float b3 = __ldg(br3);

    for (int pass = 0; pass < 2; pass++) {
        int row0 = blockIdx.x * 128 + w * 16 + pass * 8;

        float z8[8][8];
#pragma unroll
        for (int r = 0; r < 8; r++) {
            const float4* zp = reinterpret_cast<const float4*>(g_z + (row0 + r) * 8);
            float4 u = zp[0], v = zp[1];
            z8[r][0] = u.x; z8[r][1] = u.y; z8[r][2] = u.z; z8[r][3] = u.w;
            z8[r][4] = v.x; z8[r][5] = v.y; z8[r][6] = v.z; z8[r][7] = v.w;
        }
        for (int j = lane; j < 200; j += 32) {
            const float4* wp = reinterpret_cast<const float4*>(sm + K2_W1 + j * 8);
            float4 a = wp[0], b = wp[1];
            float bj = sm[K2_B1 + j];
#pragma unroll
            for (int r = 0; r < 8; r++) {
                float h = bj;
                h = fmaf(a.x, z8[r][0], h); h = fmaf(a.y, z8[r][1], h);
                h = fmaf(a.z, z8[r][2], h); h = fmaf(a.w, z8[r][3], h);
                h = fmaf(b.x, z8[r][4], h); h = fmaf(b.y, z8[r][5], h);
                h = fmaf(b.z, z8[r][6], h); h = fmaf(b.w, z8[r][7], h);
                h1w[j * 8 + r] = h * normcdff(h);
            }
        }
        __syncwarp();

        ull acc[7][4];
#pragma unroll
        for (int u = 0; u < 7; u++)
#pragma unroll
            for (int q = 0; q < 4; q++) acc[u][q] = 0ull;

        for (int q = 0; q < 200; q++) {
            const ull* hp = reinterpret_cast<const ull*>(h1w + q * 8);
            ull h01 = hp[0], h23 = hp[1], h45 = hp[2], h67 = hp[3];
#pragma unroll
            for (int u = 0; u < 7; u++) {
                int j = lane + 32 * u;
                float wv = (j < 200) ? sm[K2_W2 + j * 201 + q] : 0.f;
                ull w2 = pack2(wv, wv);
                acc[u][0] = fma2(w2, h01, acc[u][0]);
                acc[u][1] = fma2(w2, h23, acc[u][1]);
                acc[u][2] = fma2(w2, h45, acc[u][2]);
                acc[u][3] = fma2(w2, h67, acc[u][3]);
            }
        }

        float part[8];
#pragma unroll
        for (int r = 0; r < 8; r++) part[r] = 0.f;
#pragma unroll
        for (int u = 0; u < 7; u++) {
            int j = lane + 32 * u;
            if (j < 200) {
                float w3 = sm[K2_W3 + j];
                float b2j = sm[K2_B2 + j];
#pragma unroll
                for (int q = 0; q < 4; q++) {
                    float v0, v1; unpack2(acc[u][q], v0, v1);
                    v0 += b2j; v1 += b2j;
                    part[2 * q]     = fmaf(w3, v0 * normcdff(v0), part[2 * q]);
                    part[2 * q + 1] = fmaf(w3, v1 * normcdff(v1), part[2 * q + 1]);
                }
            }
        }
#pragma unroll
        for (int r = 0; r < 8; r++)
#pragma unroll
            for (int m = 16; m >= 1; m >>= 1)
                part[r] += __shfl_xor_sync(0xffffffffu, part[r], m);

        if (lane < 8) {
            float t = part[lane] + b3;
            float sg = 1.0f / (1.0f + expf(-t));
            g_T10[row0 + lane] = 0.1f + sg * (7.0f - 0.1f);
        }
        __syncwarp();
    }
}

__global__ void __launch_bounds__(128)
k3_out(const float* __restrict__ fa_in, const float* __restrict__ TR,
       const int* __restrict__ fa_len, float* __restrict__ out) {
    int lane = threadIdx.x & 31;
    int w = threadIdx.x >> 5;
    int row = blockIdx.x * 4 + w;

    float T10 = g_T10[row];
    float R1 = 1.0f / T10;
    float E = expf(-TR[row] * R1);
    float fa = fa_in[row * LL + lane];
    float xo = (1.0f - E) * sinf(fa) / (1.0f - cosf(fa) * E);

    float ssum = xo;
#pragma unroll
    for (int m = 16; m >= 1; m >>= 1) ssum += __shfl_xor_sync(0xffffffffu, ssum, m);

    float fl = (float)fa_len[row];
    out[row * LL + lane] = xo * fl / ssum;
    if (lane == 0) {
        out[BB * LL + row] = T10;       // T10
        out[BB * LL + BB + row] = 1.0f; // M0
    }
}

extern "C" void kernel_launch(void* const* d_in, const int* in_sizes, int n_in,
                              void* d_out, int out_size) {
    const float* X_fa_in    = (const float*)d_in[0];
    const float* fa_vals_in = (const float*)d_in[1];
    const float* TR_vals    = (const float*)d_in[2];
    const float* W_init     = (const float*)d_in[3];
    const float* b_init     = (const float*)d_in[4];
    const float* W1         = (const float*)d_in[5];
    const float* b1         = (const float*)d_in[6];
    const float* W2         = (const float*)d_in[7];
    const float* b2         = (const float*)d_in[8];
    const float* Wr1        = (const float*)d_in[9];
    const float* br1        = (const float*)d_in[10];
    const float* Wr2        = (const float*)d_in[11];
    const float* br2        = (const float*)d_in[12];
    const float* Wr3        = (const float*)d_in[13];
    const float* br3        = (const float*)d_in[14];
    // d_in[15] = fa_mask (unused)
    const int*   fa_len     = (const int*)d_in[16];

    float* out = (float*)d_out;

    // host-state op (not a stream op): capture-safe, deterministic, no alloc
    cudaFuncSetAttribute(k2_readout, cudaFuncAttributeMaxDynamicSharedMemorySize,
                         K2_SMEM_BYTES);

    k1_ode<<<GRID1, 32>>>(X_fa_in, fa_vals_in, fa_len, W_init, b_init, W1, b1, W2, b2);
    k2_readout<<<128, 256, K2_SMEM_BYTES>>>(Wr1, br1, Wr2, br2, Wr3, br3);
    k3_out<<<BB / 4, 128>>>(fa_vals_in, TR_vals, fa_len, out);
}

// round 15
// speedup vs baseline: 1.3736x; 1.3736x over previous
#include <cuda_runtime.h>
#include <cuda_bf16.h>
#include <math.h>

#define BB 16384
#define LL 32

typedef unsigned long long ull;

// scratch (no allocation allowed)
__device__ float g_z[BB * 8];
__device__ float g_T10[BB];

__device__ __forceinline__ ull pack2(float lo, float hi) {
    ull r; asm("mov.b64 %0,{%1,%2};" : "=l"(r) : "f"(lo), "f"(hi)); return r;
}
__device__ __forceinline__ void unpack2(ull v, float& lo, float& hi) {
    asm("mov.b64 {%0,%1},%2;" : "=f"(lo), "=f"(hi) : "l"(v));
}
__device__ __forceinline__ ull fma2(ull a, ull b, ull c) {
    ull d; asm("fma.rn.f32x2 %0,%1,%2,%3;" : "=l"(d) : "l"(a), "l"(b), "l"(c)); return d;
}
__device__ __forceinline__ ull add2(ull a, ull b) {
    ull d; asm("add.rn.f32x2 %0,%1,%2;" : "=l"(d) : "l"(a), "l"(b)); return d;
}
__device__ __forceinline__ ull shfl64(ull v, int m) {
    float lo, hi; unpack2(v, lo, hi);
    lo = __shfl_xor_sync(0xffffffffu, lo, m);
    hi = __shfl_xor_sync(0xffffffffu, hi, m);
    return pack2(lo, hi);
}

__device__ __forceinline__ float tanh_fast(float x) {
    float e = __expf(2.0f * x);
    return 1.0f - __fdividef(2.0f, e + 1.0f);
}

__device__ __forceinline__ float2 dxval(float s, float2 x0, float2 x1, float2 m0, float2 m1) {
    float s2 = s * s;
    float cx0 = 6.f * s2 - 6.f * s;
    float cm0 = 3.f * s2 - 4.f * s + 1.f;
    float cx1 = -6.f * s2 + 6.f * s;
    float cm1 = 3.f * s2 - 2.f * s;
    float2 r;
    r.x = cx0 * x0.x + cm0 * m0.x + cx1 * x1.x + cm1 * m1.x;
    r.y = cx0 * x0.y + cm0 * m0.y + cx1 * x1.y + cm1 * m1.y;
    return r;
}

// F(s,z) for TWO rows per lane; warp splits k by lane parity g (stride 2)
// and warp half kh. Packed reduce; tanh on own j-half; k reassembled by shfl.
__device__ __forceinline__ void Feval2(const ull* zA, const ull* zB,
                                       float2 dA, float2 dB,
                                       const float* w1p, const float* w2p,
                                       const ull* b1p, const float* sB2,
                                       int odd, int kh,
                                       ull* kA, ull* kB) {
    ull aA[8], aB[8];
#pragma unroll
    for (int j = 0; j < 8; j++) { aA[j] = 0ull; aB[j] = 0ull; }

#pragma unroll 8
    for (int t = 0; t < 64; t++) {
        ulonglong2 w1a = *reinterpret_cast<const ulonglong2*>(w1p + t * 16);
        ulonglong2 w1b = *reinterpret_cast<const ulonglong2*>(w1p + t * 16 + 4);
        ull bk = b1p[t * 2];

        ull accA = fma2(w1a.x, zA[0], bk);
        ull accB = fma2(w1a.x, zB[0], bk);
        accA = fma2(w1a.y, zA[1], accA);
        accB = fma2(w1a.y, zB[1], accB);
        accA = fma2(w1b.x, zA[2], accA);
        accB = fma2(w1b.x, zB[2], accB);
        accA = fma2(w1b.y, zA[3], accA);
        accB = fma2(w1b.y, zB[3], accB);
        float alo, ahi, blo, bhi;
        unpack2(accA, alo, ahi);
        unpack2(accB, blo, bhi);
        float hA = fmaxf(alo + ahi, 0.f);
        float hB = fmaxf(blo + bhi, 0.f);
        ull hhA = pack2(hA, hA);
        ull hhB = pack2(hB, hB);

        const float* base = w2p + t * 32;
        ulonglong2 c0 = *reinterpret_cast<const ulonglong2*>(base);
        ulonglong2 c1 = *reinterpret_cast<const ulonglong2*>(base + 4);
        ulonglong2 c2 = *reinterpret_cast<const ulonglong2*>(base + 8);
        ulonglong2 c3 = *reinterpret_cast<const ulonglong2*>(base + 12);
        aA[0] = fma2(c0.x, hhA, aA[0]);  aB[0] = fma2(c0.x, hhB, aB[0]);
        aA[1] = fma2(c0.y, hhA, aA[1]);  aB[1] = fma2(c0.y, hhB, aB[1]);
        aA[2] = fma2(c1.x, hhA, aA[2]);  aB[2] = fma2(c1.x, hhB, aB[2]);
        aA[3] = fma2(c1.y, hhA, aA[3]);  aB[3] = fma2(c1.y, hhB, aB[3]);
        aA[4] = fma2(c2.x, hhA, aA[4]);  aB[4] = fma2(c2.x, hhB, aB[4]);
        aA[5] = fma2(c2.y, hhA, aA[5]);  aB[5] = fma2(c2.y, hhB, aB[5]);
        aA[6] = fma2(c3.x, hhA, aA[6]);  aB[6] = fma2(c3.x, hhB, aB[6]);
        aA[7] = fma2(c3.y, hhA, aA[7]);  aB[7] = fma2(c3.y, hhB, aB[7]);
    }

    // stage 1 (packed): xor-1 role split; even lane keeps row A, odd row B
    ull t8[8];
#pragma unroll
    for (int j = 0; j < 8; j++) {
        ull give = odd ? aA[j] : aB[j];
        ull keep = odd ? aB[j] : aA[j];
        t8[j] = add2(keep, shfl64(give, 1));
    }
    // stage 2 (packed): xor-16 kh role split; lane keeps its j-half
    ull own[4];
#pragma unroll
    for (int i = 0; i < 4; i++) {
        ull give = kh ? t8[i] : t8[4 + i];
        ull keep = kh ? t8[4 + i] : t8[i];
        own[i] = add2(keep, shfl64(give, 16));
    }

    float2 dm;
    dm.x = odd ? dB.x : dA.x;
    dm.y = odd ? dB.y : dA.y;
    const float* b2p = sB2 + 8 * kh;

    float o[4];
#pragma unroll
    for (int i = 0; i < 4; i++) {
        float u0, u1; unpack2(own[i], u0, u1);
        float t0 = tanh_fast(u0 + b2p[2 * i]);
        float t1 = tanh_fast(u1 + b2p[2 * i + 1]);
        o[i] = t0 * dm.x + t1 * dm.y;
    }
    ull m0 = pack2(o[0], o[1]);
    ull m1 = pack2(o[2], o[3]);

    ull ko0 = shfl64(m0, 16);
    ull ko1 = shfl64(m1, 16);
    ull kmy[4];
    int hb = kh * 2;
    kmy[hb]           = m0;
    kmy[hb + 1]       = m1;
    kmy[hb ^ 2]       = ko0;
    kmy[(hb ^ 2) + 1] = ko1;

#pragma unroll
    for (int hh = 0; hh < 4; hh++) {
        ull ko = shfl64(kmy[hh], 1);
        kA[hh] = odd ? ko : kmy[hh];
        kB[hh] = odd ? kmy[hh] : ko;
    }
}

__device__ __forceinline__ void substep2(ull* zA, ull* zB,
                                         float2 xaA, float2 xbA, float2 m0A, float2 m1A,
                                         float2 xaB, float2 xbB, float2 m0B, float2 m1B,
                                         float s0,
                                         const float* w1p, const float* w2p,
                                         const ull* b1p, const float* sB2,
                                         int odd, int kh) {
    float2 dA1 = dxval(s0,         xaA, xbA, m0A, m1A);
    float2 dA2 = dxval(s0 + 0.25f, xaA, xbA, m0A, m1A);
    float2 dA3 = dxval(s0 + 0.5f,  xaA, xbA, m0A, m1A);
    float2 dB1 = dxval(s0,         xaB, xbB, m0B, m1B);
    float2 dB2 = dxval(s0 + 0.25f, xaB, xbB, m0B, m1B);
    float2 dB3 = dxval(s0 + 0.5f,  xaB, xbB, m0B, m1B);

    const ull C025 = pack2(0.25f, 0.25f);
    const ull C05  = pack2(0.5f, 0.5f);
    const ull C2   = pack2(2.f, 2.f);
    const ull C112 = pack2(1.f / 12.f, 1.f / 12.f);

    ull kcA[4], kcB[4], ksA[4], ksB[4], ztA[4], ztB[4];
    Feval2(zA, zB, dA1, dB1, w1p, w2p, b1p, sB2, odd, kh, kcA, kcB);
#pragma unroll
    for (int j = 0; j < 4; j++) {
        ksA[j] = kcA[j]; ztA[j] = fma2(C025, kcA[j], zA[j]);
        ksB[j] = kcB[j]; ztB[j] = fma2(C025, kcB[j], zB[j]);
    }
    Feval2(ztA, ztB, dA2, dB2, w1p, w2p, b1p, sB2, odd, kh, kcA, kcB);
#pragma unroll
    for (int j = 0; j < 4; j++) {
        ksA[j] = fma2(C2, kcA[j], ksA[j]); ztA[j] = fma2(C025, kcA[j], zA[j]);
        ksB[j] = fma2(C2, kcB[j], ksB[j]); ztB[j] = fma2(C025, kcB[j], zB[j]);
    }
    Feval2(ztA, ztB, dA2, dB2, w1p, w2p, b1p, sB2, odd, kh, kcA, kcB);
#pragma unroll
    for (int j = 0; j < 4; j++) {
        ksA[j] = fma2(C2, kcA[j], ksA[j]); ztA[j] = fma2(C05, kcA[j], zA[j]);
        ksB[j] = fma2(C2, kcB[j], ksB[j]); ztB[j] = fma2(C05, kcB[j], zB[j]);
    }
    Feval2(ztA, ztB, dA3, dB3, w1p, w2p, b1p, sB2, odd, kh, kcA, kcB);
#pragma unroll
    for (int j = 0; j < 4; j++) {
        zA[j] = fma2(C112, add2(ksA[j], kcA[j]), zA[j]);
        zB[j] = fma2(C112, add2(ksB[j], kcB[j]), zB[j]);
    }
}

__global__ void __launch_bounds__(32, 8)
k1_ode(const float* __restrict__ X_in, const float* __restrict__ fa_in,
       const int* __restrict__ fa_len,
       const float* __restrict__ W_init, const float* __restrict__ b_init,
       const float* __restrict__ W1, const float* __restrict__ b1,
       const float* __restrict__ W2, const float* __restrict__ b2) {
    // padded layouts: kh half-blocks bank-shifted by 16 B
    __shared__ __align__(16) float sW1[2052];
    __shared__ __align__(16) float sW2T[4100];
    __shared__ __align__(16) ull   sB1p[258];
    __shared__ float sB2[16];
    __shared__ float sWI[16];
    __shared__ float sBI[8];
    __shared__ float2 sX[16][33];

    int tid = threadIdx.x;   // 0..31
    for (int i = tid; i < 2048; i += 32) {
        int kk = i >> 3, e = i & 7;
        int h = kk >> 7, jr = kk & 127;
        sW1[h * 1028 + jr * 8 + e] = W1[i];
    }
    for (int i = tid; i < 16 * 256; i += 32) {
        int j = i >> 8;
        int k = i & 255;
        int h = k >> 7, jr = k & 127;
        sW2T[h * 2052 + jr * 16 + j] = W2[i];
    }
    for (int i = tid; i < 256; i += 32) {
        int h = i >> 7, jr = i & 127;
        sB1p[h * 130 + jr] = pack2(b1[i], 0.f);
    }
    if (tid < 16) sB2[tid] = b2[tid];
    if (tid < 16) sWI[tid] = W_init[tid];
    if (tid < 8)  sBI[tid] = b_init[tid];

    int g  = tid & 1;            // k-parity within half (stride 2)
    int kh = (tid >> 4) & 1;     // k-half
    int p  = (tid >> 1) & 7;     // pair id, 0..7
    int q0 = g + 2 * kh;         // lane's slot among the row's 4 lanes
    int rowA = blockIdx.x * 16 + p;
    int rowB = rowA + 8;

    const float* w2p = sW2T + kh * 2052 + g * 16;
    const float* w1p = sW1  + kh * 1028 + g * 8;
    const ull*   b1p = sB1p + kh * 130  + g;

    // prologue for both rows: mean, normalize, push-zeros-as-shift
#pragma unroll
    for (int rr = 0; rr < 2; rr++) {
        int row = rr ? rowB : rowA;
        int rib = rr ? (p + 8) : p;
        const float* Xr = X_in + row * LL;
        const float* Fr = fa_in + row * LL;
        int fl = fa_len[row];

        float s = 0.f;
        for (int t = q0; t < LL; t += 4) s += Xr[t];
        s += __shfl_xor_sync(0xffffffffu, s, 1);
        s += __shfl_xor_sync(0xffffffffu, s, 16);
        float mean = s / (float)fl;

        int shift = LL - fl;
        int li = 2 * fl - LL - 1;
        float lastX = (li >= 0) ? (Xr[li] / mean) : 0.f;
        float lastF = Fr[fl - 1];

        for (int q = q0; q < LL; q += 4) {
            float fa, xx;
            if (q < shift) { fa = lastF; xx = lastX; }
            else           { fa = Fr[q - shift]; xx = Xr[q - shift] / mean; }
            sX[rib][q] = make_float2(fa, xx);
        }
    }
    __syncwarp();

    float2 x0A = sX[p][0];
    float2 x0B = sX[p + 8][0];
    ull zA[4], zB[4];
#pragma unroll
    for (int j = 0; j < 4; j++) {
        float a0 = sBI[2 * j]     + sWI[4 * j]     * x0A.x + sWI[4 * j + 1] * x0A.y;
        float a1 = sBI[2 * j + 1] + sWI[4 * j + 2] * x0A.x + sWI[4 * j + 3] * x0A.y;
        zA[j] = pack2(a0, a1);
        float b0 = sBI[2 * j]     + sWI[4 * j]     * x0B.x + sWI[4 * j + 1] * x0B.y;
        float b1v = sBI[2 * j + 1] + sWI[4 * j + 2] * x0B.x + sWI[4 * j + 3] * x0B.y;
        zB[j] = pack2(b0, b1v);
    }

    float2 xaA = x0A, m0A = make_float2(0.f, 0.f), m1A;
    float2 xaB = x0B, m0B = make_float2(0.f, 0.f), m1B;
    for (int i = 0; i < LL - 1; i++) {
        float2 xbA = sX[p][i + 1];
        float2 xbB = sX[p + 8][i + 1];
        m1A.x = xbA.x - xaA.x;  m1A.y = xbA.y - xaA.y;
        m1B.x = xbB.x - xaB.x;  m1B.y = xbB.y - xaB.y;
        if (i == 0) { m0A = m1A; m0B = m1B; }
        substep2(zA, zB, xaA, xbA, m0A, m1A, xaB, xbB, m0B, m1B, 0.0f,
                 w1p, w2p, b1p, sB2, g, kh);
        substep2(zA, zB, xaA, xbA, m0A, m1A, xaB, xbB, m0B, m1B, 0.5f,
                 w1p, w2p, b1p, sB2, g, kh);
        m0A = m1A; m0B = m1B;
        xaA = xbA; xaB = xbB;
    }
    // all 4 lanes of the row hold identical z; lane slot q0 writes [2q0, 2q0+1]
    {
        float a0, a1, b0, b1v;
        unpack2(zA[q0], a0, a1);
        unpack2(zB[q0], b0, b1v);
        g_z[rowA * 8 + 2 * q0]     = a0;
        g_z[rowA * 8 + 2 * q0 + 1] = a1;
        g_z[rowB * 8 + 2 * q0]     = b0;
        g_z[rowB * 8 + 2 * q0 + 1] = b1v;
    }
}

// ---------------- k2: readout MLP with smem-cached Wr2 ----------------
#define K2_W2   0                    // 200*201 floats
#define K2_W1   (200 * 201)          // 1600
#define K2_B1   (K2_W1 + 1600)       // 200
#define K2_B2   (K2_B1 + 200)        // 200
#define K2_W3   (K2_B2 + 200)        // 200
#define K2_H1   (K2_W3 + 200)        // 8 warps * 1600
#define K2_SMEM_FLOATS (K2_H1 + 8 * 1600)
#define K2_SMEM_BYTES  (K2_SMEM_FLOATS * 4)

__global__ void __launch_bounds__(256, 1)
k2_readout(const float* __restrict__ Wr1, const float* __restrict__ br1,
           const float* __restrict__ Wr2, const float* __restrict__ br2,
           const float* __restrict__ Wr3, const float* __restrict__ br3) {
    extern __shared__ __align__(16) float sm[];
    int tid = threadIdx.x;
    int lane = tid & 31;
    int w = tid >> 5;

    for (int i = tid; i < 200 * 200; i += 256)
        sm[K2_W2 + (i / 200) * 201 + (i % 200)] = Wr2[i];
    for (int i = tid; i < 1600; i += 256) sm[K2_W1 + i] = Wr1[i];
    for (int i = tid; i < 200; i += 256) {
        sm[K2_B1 + i] = br1[i];
        sm[K2_B2 + i] = br2[i];
        sm[K2_W3 + i] = Wr3[i];
    }
    __syncthreads();

    float* h1w = sm + K2_H1 + w * 1600;
    float b3 = __ldg(br3);

    for (int pass = 0; pass < 2; pass++) {
        int row0 = blockIdx.x * 128 + w * 16 + pass * 8;

        float z8[8][8];
#pragma unroll
        for (int r = 0; r < 8; r++) {
            const float4* zp = reinterpret_cast<const float4*>(g_z + (row0 + r) * 8);
            float4 u = zp[0], v = zp[1];
            z8[r][0] = u.x; z8[r][1] = u.y; z8[r][2] = u.z; z8[r][3] = u.w;
            z8[r][4] = v.x; z8[r][5] = v.y; z8[r][6] = v.z; z8[r][7] = v.w;
        }
        for (int j = lane; j < 200; j += 32) {
            const float4* wp = reinterpret_cast<const float4*>(sm + K2_W1 + j * 8);
            float4 a = wp[0], b = wp[1];
            float bj = sm[K2_B1 + j];
#pragma unroll
            for (int r = 0; r < 8; r++) {
                float h = bj;
                h = fmaf(a.x, z8[r][0], h); h = fmaf(a.y, z8[r][1], h);
                h = fmaf(a.z, z8[r][2], h); h = fmaf(a.w, z8[r][3], h);
                h = fmaf(b.x, z8[r][4], h); h = fmaf(b.y, z8[r][5], h);
                h = fmaf(b.z, z8[r][6], h); h = fmaf(b.w, z8[r][7], h);
                h1w[j * 8 + r] = h * normcdff(h);
            }
        }
        __syncwarp();

        ull acc[7][4];
#pragma unroll
        for (int u = 0; u < 7; u++)
#pragma unroll
            for (int q = 0; q < 4; q++) acc[u][q] = 0ull;

        for (int q = 0; q < 200; q++) {
            const ull* hp = reinterpret_cast<const ull*>(h1w + q * 8);
            ull h01 = hp[0], h23 = hp[1], h45 = hp[2], h67 = hp[3];
#pragma unroll
            for (int u = 0; u < 7; u++) {
                int j = lane + 32 * u;
                float wv = (j < 200) ? sm[K2_W2 + j * 201 + q] : 0.f;
                ull w2 = pack2(wv, wv);
                acc[u][0] = fma2(w2, h01, acc[u][0]);
                acc[u][1] = fma2(w2, h23, acc[u][1]);
                acc[u][2] = fma2(w2, h45, acc[u][2]);
                acc[u][3] = fma2(w2, h67, acc[u][3]);
            }
        }

        float part[8];
#pragma unroll
        for (int r = 0; r < 8; r++) part[r] = 0.f;
#pragma unroll
        for (int u = 0; u < 7; u++) {
            int j = lane + 32 * u;
            if (j < 200) {
                float w3 = sm[K2_W3 + j];
                float b2j = sm[K2_B2 + j];
#pragma unroll
                for (int q = 0; q < 4; q++) {
                    float v0, v1; unpack2(acc[u][q], v0, v1);
                    v0 += b2j; v1 += b2j;
                    part[2 * q]     = fmaf(w3, v0 * normcdff(v0), part[2 * q]);
                    part[2 * q + 1] = fmaf(w3, v1 * normcdff(v1), part[2 * q + 1]);
                }
            }
        }
#pragma unroll
        for (int r = 0; r < 8; r++)
#pragma unroll
            for (int m = 16; m >= 1; m >>= 1)
                part[r] += __shfl_xor_sync(0xffffffffu, part[r], m);

        if (lane < 8) {
            float t = part[lane] + b3;
            float sg = 1.0f / (1.0f + expf(-t));
            g_T10[row0 + lane] = 0.1f + sg * (7.0f - 0.1f);
        }
        __syncwarp();
    }
}

__global__ void __launch_bounds__(128)
k3_out(const float* __restrict__ fa_in, const float* __restrict__ TR,
       const int* __restrict__ fa_len, float* __restrict__ out) {
    int lane = threadIdx.x & 31;
    int w = threadIdx.x >> 5;
    int row = blockIdx.x * 4 + w;

    float T10 = g_T10[row];
    float R1 = 1.0f / T10;
    float E = expf(-TR[row] * R1);
    float fa = fa_in[row * LL + lane];
    float xo = (1.0f - E) * sinf(fa) / (1.0f - cosf(fa) * E);

    float ssum = xo;
#pragma unroll
    for (int m = 16; m >= 1; m >>= 1) ssum += __shfl_xor_sync(0xffffffffu, ssum, m);

    float fl = (float)fa_len[row];
    out[row * LL + lane] = xo * fl / ssum;
    if (lane == 0) {
        out[BB * LL + row] = T10;       // T10
        out[BB * LL + BB + row] = 1.0f; // M0
    }
}

extern "C" void kernel_launch(void* const* d_in, const int* in_sizes, int n_in,
                              void* d_out, int out_size) {
    const float* X_fa_in    = (const float*)d_in[0];
    const float* fa_vals_in = (const float*)d_in[1];
    const float* TR_vals    = (const float*)d_in[2];
    const float* W_init     = (const float*)d_in[3];
    const float* b_init     = (const float*)d_in[4];
    const float* W1         = (const float*)d_in[5];
    const float* b1         = (const float*)d_in[6];
    const float* W2         = (const float*)d_in[7];
    const float* b2         = (const float*)d_in[8];
    const float* Wr1        = (const float*)d_in[9];
    const float* br1        = (const float*)d_in[10];
    const float* Wr2        = (const float*)d_in[11];
    const float* br2        = (const float*)d_in[12];
    const float* Wr3        = (const float*)d_in[13];
    const float* br3        = (const float*)d_in[14];
    // d_in[15] = fa_mask (unused)
    const int*   fa_len     = (const int*)d_in[16];

    float* out = (float*)d_out;

    // host-state op (not a stream op): capture-safe, deterministic, no alloc
    cudaFuncSetAttribute(k2_readout, cudaFuncAttributeMaxDynamicSharedMemorySize,
                         K2_SMEM_BYTES);

    k1_ode<<<BB / 16, 32>>>(X_fa_in, fa_vals_in, fa_len, W_init, b_init, W1, b1, W2, b2);
    k2_readout<<<128, 256, K2_SMEM_BYTES>>>(Wr1, br1, Wr2, br2, Wr3, br3);
    k3_out<<<BB / 4, 128>>>(fa_vals_in, TR_vals, fa_len, out);
}

// round 16
// speedup vs baseline: 1.3986x; 1.0183x over previous
#include <cuda_runtime.h>
#include <cuda_bf16.h>
#include <math.h>

#define BB 16384
#define LL 32

typedef unsigned long long ull;

// scratch (no allocation allowed)
__device__ float g_z[BB * 8];
__device__ float g_T10[BB];

__device__ __forceinline__ ull pack2(float lo, float hi) {
    ull r; asm("mov.b64 %0,{%1,%2};" : "=l"(r) : "f"(lo), "f"(hi)); return r;
}
__device__ __forceinline__ void unpack2(ull v, float& lo, float& hi) {
    asm("mov.b64 {%0,%1},%2;" : "=f"(lo), "=f"(hi) : "l"(v));
}
__device__ __forceinline__ ull fma2(ull a, ull b, ull c) {
    ull d; asm("fma.rn.f32x2 %0,%1,%2,%3;" : "=l"(d) : "l"(a), "l"(b), "l"(c)); return d;
}
__device__ __forceinline__ ull add2(ull a, ull b) {
    ull d; asm("add.rn.f32x2 %0,%1,%2;" : "=l"(d) : "l"(a), "l"(b)); return d;
}
__device__ __forceinline__ ull shfl64(ull v, int m) {
    float lo, hi; unpack2(v, lo, hi);
    lo = __shfl_xor_sync(0xffffffffu, lo, m);
    hi = __shfl_xor_sync(0xffffffffu, hi, m);
    return pack2(lo, hi);
}

__device__ __forceinline__ float tanh_fast(float x) {
    float e = __expf(2.0f * x);
    return 1.0f - __fdividef(2.0f, e + 1.0f);
}

__device__ __forceinline__ float2 dxval(float s, float2 x0, float2 x1, float2 m0, float2 m1) {
    float s2 = s * s;
    float cx0 = 6.f * s2 - 6.f * s;
    float cm0 = 3.f * s2 - 4.f * s + 1.f;
    float cx1 = -6.f * s2 + 6.f * s;
    float cm1 = 3.f * s2 - 2.f * s;
    float2 r;
    r.x = cx0 * x0.x + cm0 * m0.x + cx1 * x1.x + cm1 * m1.x;
    r.y = cx0 * x0.y + cm0 * m0.y + cx1 * x1.y + cm1 * m1.y;
    return r;
}

// duplicate packed (z0,z1) state into component-dup form (zj,zj)
__device__ __forceinline__ void dup4(const ull* z, ull* zd) {
#pragma unroll
    for (int j = 0; j < 4; j++) {
        float lo, hi; unpack2(z[j], lo, hi);
        zd[2 * j]     = pack2(lo, lo);
        zd[2 * j + 1] = pack2(hi, hi);
    }
}

// F(s,z) for TWO rows per lane; warp splits k by lane parity g (stride 2)
// and warp half kh. k-PAIR packing: W1 stored as (W1[k],W1[k+2]) pairs so
// one packed chain computes BOTH k's layer-1 dots with no horizontal add.
// ReLU done packed via h+|h| with the 0.5 folded into W2 (bit-exact).
// W2 accumulation, reduce and epilogue identical to the R11 champion.
__device__ __forceinline__ void Feval2(const ull* zdA, const ull* zdB,
                                       float2 dA, float2 dB,
                                       const ull* w1pp, const float* w2p,
                                       const ull* b1pp, const float* sB2,
                                       int odd, int kh,
                                       ull* kA, ull* kB) {
    const ull SMASK = 0x7FFFFFFF7FFFFFFFULL;
    ull aA[8], aB[8];
#pragma unroll
    for (int j = 0; j < 8; j++) { aA[j] = 0ull; aB[j] = 0ull; }

#pragma unroll 4
    for (int u = 0; u < 32; u++) {
        ulonglong2 w01 = *reinterpret_cast<const ulonglong2*>(w1pp + u * 8);
        ulonglong2 w23 = *reinterpret_cast<const ulonglong2*>(w1pp + u * 8 + 2);
        ulonglong2 w45 = *reinterpret_cast<const ulonglong2*>(w1pp + u * 8 + 4);
        ulonglong2 w67 = *reinterpret_cast<const ulonglong2*>(w1pp + u * 8 + 6);
        ull bk = b1pp[u];

        // row A: two parallel 4-deep chains, no horizontal add
        ull paA = fma2(w01.y, zdA[1], fma2(w01.x, zdA[0], bk));
        paA = fma2(w23.y, zdA[3], fma2(w23.x, zdA[2], paA));
        ull pbA = fma2(w45.y, zdA[5], fma2(w45.x, zdA[4], 0ull));
        pbA = fma2(w67.y, zdA[7], fma2(w67.x, zdA[6], pbA));
        ull hA = add2(paA, pbA);
        ull rA = add2(hA, hA & SMASK);    // (2*relu(h_k1), 2*relu(h_k2))
        float a1, a2; unpack2(rA, a1, a2);
        ull h1A = pack2(a1, a1), h2A = pack2(a2, a2);

        // row B
        ull paB = fma2(w01.y, zdB[1], fma2(w01.x, zdB[0], bk));
        paB = fma2(w23.y, zdB[3], fma2(w23.x, zdB[2], paB));
        ull pbB = fma2(w45.y, zdB[5], fma2(w45.x, zdB[4], 0ull));
        pbB = fma2(w67.y, zdB[7], fma2(w67.x, zdB[6], pbB));
        ull hB = add2(paB, pbB);
        ull rB = add2(hB, hB & SMASK);
        float b1f, b2f; unpack2(rB, b1f, b2f);
        ull h1B = pack2(b1f, b1f), h2B = pack2(b2f, b2f);

        // W2 rows for k_lo and k_hi (values prescaled by 0.5)
        const float* base = w2p + u * 64;
        ulonglong2 c0 = *reinterpret_cast<const ulonglong2*>(base);
        ulonglong2 c1 = *reinterpret_cast<const ulonglong2*>(base + 4);
        ulonglong2 c2 = *reinterpret_cast<const ulonglong2*>(base + 8);
        ulonglong2 c3 = *reinterpret_cast<const ulonglong2*>(base + 12);
        ulonglong2 e0 = *reinterpret_cast<const ulonglong2*>(base + 32);
        ulonglong2 e1 = *reinterpret_cast<const ulonglong2*>(base + 36);
        ulonglong2 e2 = *reinterpret_cast<const ulonglong2*>(base + 40);
        ulonglong2 e3 = *reinterpret_cast<const ulonglong2*>(base + 44);

        aA[0] = fma2(c0.x, h1A, aA[0]);  aB[0] = fma2(c0.x, h1B, aB[0]);
        aA[1] = fma2(c0.y, h1A, aA[1]);  aB[1] = fma2(c0.y, h1B, aB[1]);
        aA[2] = fma2(c1.x, h1A, aA[2]);  aB[2] = fma2(c1.x, h1B, aB[2]);
        aA[3] = fma2(c1.y, h1A, aA[3]);  aB[3] = fma2(c1.y, h1B, aB[3]);
        aA[4] = fma2(c2.x, h1A, aA[4]);  aB[4] = fma2(c2.x, h1B, aB[4]);
        aA[5] = fma2(c2.y, h1A, aA[5]);  aB[5] = fma2(c2.y, h1B, aB[5]);
        aA[6] = fma2(c3.x, h1A, aA[6]);  aB[6] = fma2(c3.x, h1B, aB[6]);
        aA[7] = fma2(c3.y, h1A, aA[7]);  aB[7] = fma2(c3.y, h1B, aB[7]);

        aA[0] = fma2(e0.x, h2A, aA[0]);  aB[0] = fma2(e0.x, h2B, aB[0]);
        aA[1] = fma2(e0.y, h2A, aA[1]);  aB[1] = fma2(e0.y, h2B, aB[1]);
        aA[2] = fma2(e1.x, h2A, aA[2]);  aB[2] = fma2(e1.x, h2B, aB[2]);
        aA[3] = fma2(e1.y, h2A, aA[3]);  aB[3] = fma2(e1.y, h2B, aB[3]);
        aA[4] = fma2(e2.x, h2A, aA[4]);  aB[4] = fma2(e2.x, h2B, aB[4]);
        aA[5] = fma2(e2.y, h2A, aA[5]);  aB[5] = fma2(e2.y, h2B, aB[5]);
        aA[6] = fma2(e3.x, h2A, aA[6]);  aB[6] = fma2(e3.x, h2B, aB[6]);
        aA[7] = fma2(e3.y, h2A, aA[7]);  aB[7] = fma2(e3.y, h2B, aB[7]);
    }

    // stage 1 (packed): xor-1 role split; even lane keeps row A, odd row B
    ull t8[8];
#pragma unroll
    for (int j = 0; j < 8; j++) {
        ull give = odd ? aA[j] : aB[j];
        ull keep = odd ? aB[j] : aA[j];
        t8[j] = add2(keep, shfl64(give, 1));
    }
    // stage 2 (packed): xor-16 kh role split; lane keeps its j-half
    ull own[4];
#pragma unroll
    for (int i = 0; i < 4; i++) {
        ull give = kh ? t8[i] : t8[4 + i];
        ull keep = kh ? t8[4 + i] : t8[i];
        own[i] = add2(keep, shfl64(give, 16));
    }

    float2 dm;
    dm.x = odd ? dB.x : dA.x;
    dm.y = odd ? dB.y : dA.y;
    const float* b2p = sB2 + 8 * kh;

    float o[4];
#pragma unroll
    for (int i = 0; i < 4; i++) {
        float u0, u1; unpack2(own[i], u0, u1);
        float t0 = tanh_fast(u0 + b2p[2 * i]);
        float t1 = tanh_fast(u1 + b2p[2 * i + 1]);
        o[i] = t0 * dm.x + t1 * dm.y;
    }
    ull m0 = pack2(o[0], o[1]);
    ull m1 = pack2(o[2], o[3]);

    ull ko0 = shfl64(m0, 16);
    ull ko1 = shfl64(m1, 16);
    ull kmy[4];
    int hb = kh * 2;
    kmy[hb]           = m0;
    kmy[hb + 1]       = m1;
    kmy[hb ^ 2]       = ko0;
    kmy[(hb ^ 2) + 1] = ko1;

#pragma unroll
    for (int hh = 0; hh < 4; hh++) {
        ull ko = shfl64(kmy[hh], 1);
        kA[hh] = odd ? ko : kmy[hh];
        kB[hh] = odd ? kmy[hh] : ko;
    }
}

__device__ __forceinline__ void substep2(ull* zA, ull* zB,
                                         float2 xaA, float2 xbA, float2 m0A, float2 m1A,
                                         float2 xaB, float2 xbB, float2 m0B, float2 m1B,
                                         float s0,
                                         const ull* w1pp, const float* w2p,
                                         const ull* b1pp, const float* sB2,
                                         int odd, int kh) {
    float2 dA1 = dxval(s0,         xaA, xbA, m0A, m1A);
    float2 dA2 = dxval(s0 + 0.25f, xaA, xbA, m0A, m1A);
    float2 dA3 = dxval(s0 + 0.5f,  xaA, xbA, m0A, m1A);
    float2 dB1 = dxval(s0,         xaB, xbB, m0B, m1B);
    float2 dB2 = dxval(s0 + 0.25f, xaB, xbB, m0B, m1B);
    float2 dB3 = dxval(s0 + 0.5f,  xaB, xbB, m0B, m1B);

    const ull C025 = pack2(0.25f, 0.25f);
    const ull C05  = pack2(0.5f, 0.5f);
    const ull C2   = pack2(2.f, 2.f);
    const ull C112 = pack2(1.f / 12.f, 1.f / 12.f);

    ull kcA[4], kcB[4], ksA[4], ksB[4], ztA[4], ztB[4];
    ull zdA[8], zdB[8];

    dup4(zA, zdA); dup4(zB, zdB);
    Feval2(zdA, zdB, dA1, dB1, w1pp, w2p, b1pp, sB2, odd, kh, kcA, kcB);
#pragma unroll
    for (int j = 0; j < 4; j++) {
        ksA[j] = kcA[j]; ztA[j] = fma2(C025, kcA[j], zA[j]);
        ksB[j] = kcB[j]; ztB[j] = fma2(C025, kcB[j], zB[j]);
    }
    dup4(ztA, zdA); dup4(ztB, zdB);
    Feval2(zdA, zdB, dA2, dB2, w1pp, w2p, b1pp, sB2, odd, kh, kcA, kcB);
#pragma unroll
    for (int j = 0; j < 4; j++) {
        ksA[j] = fma2(C2, kcA[j], ksA[j]); ztA[j] = fma2(C025, kcA[j], zA[j]);
        ksB[j] = fma2(C2, kcB[j], ksB[j]); ztB[j] = fma2(C025, kcB[j], zB[j]);
    }
    dup4(ztA, zdA); dup4(ztB, zdB);
    Feval2(zdA, zdB, dA2, dB2, w1pp, w2p, b1pp, sB2, odd, kh, kcA, kcB);
#pragma unroll
    for (int j = 0; j < 4; j++) {
        ksA[j] = fma2(C2, kcA[j], ksA[j]); ztA[j] = fma2(C05, kcA[j], zA[j]);
        ksB[j] = fma2(C2, kcB[j], ksB[j]); ztB[j] = fma2(C05, kcB[j], zB[j]);
    }
    dup4(ztA, zdA); dup4(ztB, zdB);
    Feval2(zdA, zdB, dA3, dB3, w1pp, w2p, b1pp, sB2, odd, kh, kcA, kcB);
#pragma unroll
    for (int j = 0; j < 4; j++) {
        zA[j] = fma2(C112, add2(ksA[j], kcA[j]), zA[j]);
        zB[j] = fma2(C112, add2(ksB[j], kcB[j]), zB[j]);
    }
}

__global__ void __launch_bounds__(32, 8)
k1_ode(const float* __restrict__ X_in, const float* __restrict__ fa_in,
       const int* __restrict__ fa_len,
       const float* __restrict__ W_init, const float* __restrict__ b_init,
       const float* __restrict__ W1, const float* __restrict__ b1,
       const float* __restrict__ W2, const float* __restrict__ b2) {
    // W1 k-pair packs: 4 lane classes (kh,g), class stride 260 ull
    // (2080 B == 32 mod 128 -> class bases at banks 0/32/64/96: conflict-free)
    __shared__ __align__(16) ull   sW1P[4 * 260];
    // W2T with kh half padding (R11 layout), values prescaled by 0.5
    __shared__ __align__(16) float sW2T[4100];
    // b1 k-pairs: class stride 33 ull (264 B -> bank starts 0/8/16/24 B)
    __shared__ __align__(16) ull   sB1P[4 * 33];
    __shared__ float sB2[16];
    __shared__ float sWI[16];
    __shared__ float sBI[8];
    __shared__ float2 sX[16][33];

    int tid = threadIdx.x;   // 0..31
    // W1 pairs: class c = kh*2+g; k_lo = kh*128 + g + 4u, k_hi = k_lo+2
    for (int i = tid; i < 1024; i += 32) {
        int c = i >> 8;          // 0..3
        int rem = i & 255;
        int u = rem >> 3, j = rem & 7;
        int gg = c & 1, hh = c >> 1;
        int klo = hh * 128 + gg + 4 * u;
        sW1P[c * 260 + u * 8 + j] = pack2(W1[klo * 8 + j], W1[(klo + 2) * 8 + j]);
    }
    // W2 transposed [k][j] with kh half padding; prescale by 0.5 (relu trick)
    for (int i = tid; i < 16 * 256; i += 32) {
        int j = i >> 8;
        int k = i & 255;
        int h = k >> 7, jr = k & 127;
        sW2T[h * 2052 + jr * 16 + j] = 0.5f * W2[i];
    }
    // b1 pairs
    for (int i = tid; i < 128; i += 32) {
        int c = i >> 5, u = i & 31;
        int gg = c & 1, hh = c >> 1;
        int klo = hh * 128 + gg + 4 * u;
        sB1P[c * 33 + u] = pack2(b1[klo], b1[klo + 2]);
    }
    if (tid < 16) sB2[tid] = b2[tid];
    if (tid < 16) sWI[tid] = W_init[tid];
    if (tid < 8)  sBI[tid] = b_init[tid];

    int g  = tid & 1;            // k-parity within half (stride 2)
    int kh = (tid >> 4) & 1;     // k-half
    int p  = (tid >> 1) & 7;     // pair id, 0..7
    int q0 = g + 2 * kh;         // lane's slot among the row's 4 lanes
    int rowA = blockIdx.x * 16 + p;
    int rowB = rowA + 8;

    int cls = kh * 2 + g;
    const ull*   w1pp = sW1P + cls * 260;
    const ull*   b1pp = sB1P + cls * 33;
    const float* w2p  = sW2T + kh * 2052 + g * 16;

    // prologue for both rows: mean, normalize, push-zeros-as-shift
#pragma unroll
    for (int rr = 0; rr < 2; rr++) {
        int row = rr ? rowB : rowA;
        int rib = rr ? (p + 8) : p;
        const float* Xr = X_in + row * LL;
        const float* Fr = fa_in + row * LL;
        int fl = fa_len[row];

        float s = 0.f;
        for (int t = q0; t < LL; t += 4) s += Xr[t];
        s += __shfl_xor_sync(0xffffffffu, s, 1);
        s += __shfl_xor_sync(0xffffffffu, s, 16);
        float mean = s / (float)fl;

        int shift = LL - fl;
        int li = 2 * fl - LL - 1;
        float lastX = (li >= 0) ? (Xr[li] / mean) : 0.f;
        float lastF = Fr[fl - 1];

        for (int q = q0; q < LL; q += 4) {
            float fa, xx;
            if (q < shift) { fa = lastF; xx = lastX; }
            else           { fa = Fr[q - shift]; xx = Xr[q - shift] / mean; }
            sX[rib][q] = make_float2(fa, xx);
        }
    }
    __syncwarp();

    float2 x0A = sX[p][0];
    float2 x0B = sX[p + 8][0];
    ull zA[4], zB[4];
#pragma unroll
    for (int j = 0; j < 4; j++) {
        float a0 = sBI[2 * j]     + sWI[4 * j]     * x0A.x + sWI[4 * j + 1] * x0A.y;
        float a1 = sBI[2 * j + 1] + sWI[4 * j + 2] * x0A.x + sWI[4 * j + 3] * x0A.y;
        zA[j] = pack2(a0, a1);
        float b0 = sBI[2 * j]     + sWI[4 * j]     * x0B.x + sWI[4 * j + 1] * x0B.y;
        float b1v = sBI[2 * j + 1] + sWI[4 * j + 2] * x0B.x + sWI[4 * j + 3] * x0B.y;
        zB[j] = pack2(b0, b1v);
    }

    float2 xaA = x0A, m0A = make_float2(0.f, 0.f), m1A;
    float2 xaB = x0B, m0B = make_float2(0.f, 0.f), m1B;
    for (int i = 0; i < LL - 1; i++) {
        float2 xbA = sX[p][i + 1];
        float2 xbB = sX[p + 8][i + 1];
        m1A.x = xbA.x - xaA.x;  m1A.y = xbA.y - xaA.y;
        m1B.x = xbB.x - xaB.x;  m1B.y = xbB.y - xaB.y;
        if (i == 0) { m0A = m1A; m0B = m1B; }
        substep2(zA, zB, xaA, xbA, m0A, m1A, xaB, xbB, m0B, m1B, 0.0f,
                 w1pp, w2p, b1pp, sB2, g, kh);
        substep2(zA, zB, xaA, xbA, m0A, m1A, xaB, xbB, m0B, m1B, 0.5f,
                 w1pp, w2p, b1pp, sB2, g, kh);
        m0A = m1A; m0B = m1B;
        xaA = xbA; xaB = xbB;
    }
    // all 4 lanes of the row hold identical z; lane slot q0 writes [2q0, 2q0+1]
    {
        float a0, a1, b0, b1v;
        unpack2(zA[q0], a0, a1);
        unpack2(zB[q0], b0, b1v);
        g_z[rowA * 8 + 2 * q0]     = a0;
        g_z[rowA * 8 + 2 * q0 + 1] = a1;
        g_z[rowB * 8 + 2 * q0]     = b0;
        g_z[rowB * 8 + 2 * q0 + 1] = b1v;
    }
}

// ---------------- k2: readout MLP with smem-cached Wr2 ----------------
#define K2_W2   0                    // 200*201 floats
#define K2_W1   (200 * 201)          // 1600
#define K2_B1   (K2_W1 + 1600)       // 200
#define K2_B2   (K2_B1 + 200)        // 200
#define K2_W3   (K2_B2 + 200)        // 200
#define K2_H1   (K2_W3 + 200)        // 8 warps * 1600
#define K2_SMEM_FLOATS (K2_H1 + 8 * 1600)
#define K2_SMEM_BYTES  (K2_SMEM_FLOATS * 4)

__global__ void __launch_bounds__(256, 1)
k2_readout(const float* __restrict__ Wr1, const float* __restrict__ br1,
           const float* __restrict__ Wr2, const float* __restrict__ br2,
           const float* __restrict__ Wr3, const float* __restrict__ br3) {
    extern __shared__ __align__(16) float sm[];
    int tid = threadIdx.x;
    int lane = tid & 31;
    int w = tid >> 5;

    for (int i = tid; i < 200 * 200; i += 256)
        sm[K2_W2 + (i / 200) * 201 + (i % 200)] = Wr2[i];
    for (int i = tid; i < 1600; i += 256) sm[K2_W1 + i] = Wr1[i];
    for (int i = tid; i < 200; i += 256) {
        sm[K2_B1 + i] = br1[i];
        sm[K2_B2 + i] = br2[i];
        sm[K2_W3 + i] = Wr3[i];
    }
    __syncthreads();

    float* h1w = sm + K2_H1 + w * 1600;
    float b3 = __ldg(br3);

    for (int pass = 0; pass < 2; pass++) {
        int row0 = blockIdx.x * 128 + w * 16 + pass * 8;

        float z8[8][8];
#pragma unroll
        for (int r = 0; r < 8; r++) {
            const float4* zp = reinterpret_cast<const float4*>(g_z + (row0 + r) * 8);
            float4 u = zp[0], v = zp[1];
            z8[r][0] = u.x; z8[r][1] = u.y; z8[r][2] = u.z; z8[r][3] = u.w;
            z8[r][4] = v.x; z8[r][5] = v.y; z8[r][6] = v.z; z8[r][7] = v.w;
        }
        for (int j = lane; j < 200; j += 32) {
            const float4* wp = reinterpret_cast<const float4*>(sm + K2_W1 + j * 8);
            float4 a = wp[0], b = wp[1];
            float bj = sm[K2_B1 + j];
#pragma unroll
            for (int r = 0; r < 8; r++) {
                float h = bj;
                h = fmaf(a.x, z8[r][0], h); h = fmaf(a.y, z8[r][1], h);
                h = fmaf(a.z, z8[r][2], h); h = fmaf(a.w, z8[r][3], h);
                h = fmaf(b.x, z8[r][4], h); h = fmaf(b.y, z8[r][5], h);
                h = fmaf(b.z, z8[r][6], h); h = fmaf(b.w, z8[r][7], h);
                h1w[j * 8 + r] = h * normcdff(h);
            }
        }
        __syncwarp();

        ull acc[7][4];
#pragma unroll
        for (int u = 0; u < 7; u++)
#pragma unroll
            for (int q = 0; q < 4; q++) acc[u][q] = 0ull;

        for (int q = 0; q < 200; q++) {
            const ull* hp = reinterpret_cast<const ull*>(h1w + q * 8);
            ull h01 = hp[0], h23 = hp[1], h45 = hp[2], h67 = hp[3];
#pragma unroll
            for (int u = 0; u < 7; u++) {
                int j = lane + 32 * u;
                float wv = (j < 200) ? sm[K2_W2 + j * 201 + q] : 0.f;
                ull w2 = pack2(wv, wv);
                acc[u][0] = fma2(w2, h01, acc[u][0]);
                acc[u][1] = fma2(w2, h23, acc[u][1]);
                acc[u][2] = fma2(w2, h45, acc[u][2]);
                acc[u][3] = fma2(w2, h67, acc[u][3]);
            }
        }

        float part[8];
#pragma unroll
        for (int r = 0; r < 8; r++) part[r] = 0.f;
#pragma unroll
        for (int u = 0; u < 7; u++) {
            int j = lane + 32 * u;
            if (j < 200) {
                float w3 = sm[K2_W3 + j];
                float b2j = sm[K2_B2 + j];
#pragma unroll
                for (int q = 0; q < 4; q++) {
                    float v0, v1; unpack2(acc[u][q], v0, v1);
                    v0 += b2j; v1 += b2j;
                    part[2 * q]     = fmaf(w3, v0 * normcdff(v0), part[2 * q]);
                    part[2 * q + 1] = fmaf(w3, v1 * normcdff(v1), part[2 * q + 1]);
                }
            }
        }
#pragma unroll
        for (int r = 0; r < 8; r++)
#pragma unroll
            for (int m = 16; m >= 1; m >>= 1)
                part[r] += __shfl_xor_sync(0xffffffffu, part[r], m);

        if (lane < 8) {
            float t = part[lane] + b3;
            float sg = 1.0f / (1.0f + expf(-t));
            g_T10[row0 + lane] = 0.1f + sg * (7.0f - 0.1f);
        }
        __syncwarp();
    }
}

__global__ void __launch_bounds__(128)
k3_out(const float* __restrict__ fa_in, const float* __restrict__ TR,
       const int* __restrict__ fa_len, float* __restrict__ out) {
    int lane = threadIdx.x & 31;
    int w = threadIdx.x >> 5;
    int row = blockIdx.x * 4 + w;

    float T10 = g_T10[row];
    float R1 = 1.0f / T10;
    float E = expf(-TR[row] * R1);
    float fa = fa_in[row * LL + lane];
    float xo = (1.0f - E) * sinf(fa) / (1.0f - cosf(fa) * E);

    float ssum = xo;
#pragma unroll
    for (int m = 16; m >= 1; m >>= 1) ssum += __shfl_xor_sync(0xffffffffu, ssum, m);

    float fl = (float)fa_len[row];
    out[row * LL + lane] = xo * fl / ssum;
    if (lane == 0) {
        out[BB * LL + row] = T10;       // T10
        out[BB * LL + BB + row] = 1.0f; // M0
    }
}

extern "C" void kernel_launch(void* const* d_in, const int* in_sizes, int n_in,
                              void* d_out, int out_size) {
    const float* X_fa_in    = (const float*)d_in[0];
    const float* fa_vals_in = (const float*)d_in[1];
    const float* TR_vals    = (const float*)d_in[2];
    const float* W_init     = (const float*)d_in[3];
    const float* b_init     = (const float*)d_in[4];
    const float* W1         = (const float*)d_in[5];
    const float* b1         = (const float*)d_in[6];
    const float* W2         = (const float*)d_in[7];
    const float* b2         = (const float*)d_in[8];
    const float* Wr1        = (const float*)d_in[9];
    const float* br1        = (const float*)d_in[10];
    const float* Wr2        = (const float*)d_in[11];
    const float* br2        = (const float*)d_in[12];
    const float* Wr3        = (const float*)d_in[13];
    const float* br3        = (const float*)d_in[14];
    // d_in[15] = fa_mask (unused)
    const int*   fa_len     = (const int*)d_in[16];

    float* out = (float*)d_out;

    // host-state op (not a stream op): capture-safe, deterministic, no alloc
    cudaFuncSetAttribute(k2_readout, cudaFuncAttributeMaxDynamicSharedMemorySize,
                         K2_SMEM_BYTES);

    k1_ode<<<BB / 16, 32>>>(X_fa_in, fa_vals_in, fa_len, W_init, b_init, W1, b1, W2, b2);
    k2_readout<<<128, 256, K2_SMEM_BYTES>>>(Wr1, br1, Wr2, br2, Wr3, br3);
    k3_out<<<BB / 4, 128>>>(fa_vals_in, TR_vals, fa_len, out);
}